// round 3
// baseline (speedup 1.0000x reference)
#include <cuda_runtime.h>

#define BB 2
#define LSEQ 2048
#define DM 512
#define DI 1024
#define DSTATE 16
#define DTR 32
#define FF 1024
#define NL 2
#define M_TOT (BB*LSEQ)   // 4096

// ---------------- scratch (static device globals; no allocation) ----------------
__device__ float g_xz [BB*LSEQ*2*DI];   // in_proj output: [B,L,2*DI] (xin | z)
__device__ float g_xc [BB*LSEQ*DI];     // conv+silu, [B,L,DI]
__device__ float g_xcT[BB*LSEQ*DI];     // conv+silu, transposed [B,DI,L]
__device__ float g_dbl[BB*LSEQ*64];     // x_proj output [B*L, 64] (dt|B|C)
__device__ float g_bc [BB*LSEQ*32];     // interleaved (B,C) pairs [B*L][16] float2
__device__ float g_dtT[BB*LSEQ*DI];     // softplus(dt) transposed [B,DI,L]
__device__ float g_yT [BB*LSEQ*DI];     // scan output transposed [B,DI,L]
__device__ float g_yg [BB*LSEQ*DI];     // gated y [B,L,DI]
__device__ float g_x1 [BB*LSEQ*DM];
__device__ float g_x2 [BB*LSEQ*DM];
__device__ float g_ff [BB*LSEQ*FF];

__device__ __forceinline__ float siluf(float x) { return x / (1.f + __expf(-x)); }

// ---------------- generic fp32 SGEMM: C = (A (+A2)) * W^T (+bias)(relu) ----------
// A: [M,K] row-major, W: [N,K] row-major, C: [M,N]. All dims divide tiles.
template<int BM, int BN, int BK, int TM, int TN>
__global__ __launch_bounds__((BM/TM)*(BN/TN))
void sgemm_kernel(const float* __restrict__ A, const float* __restrict__ A2,
                  const float* __restrict__ W, const float* __restrict__ bias,
                  float* __restrict__ C, int M, int N, int K, int relu)
{
    constexpr int THREADS = (BM/TM)*(BN/TN);
    __shared__ __align__(16) float As[BK][BM];
    __shared__ __align__(16) float Bs[BK][BN];
    const int tid = threadIdx.x;
    const int bm = blockIdx.y * BM;
    const int bn = blockIdx.x * BN;
    const int tni = tid % (BN/TN);
    const int tmi = tid / (BN/TN);

    float acc[TM][TN];
#pragma unroll
    for (int i = 0; i < TM; i++)
#pragma unroll
        for (int j = 0; j < TN; j++) acc[i][j] = 0.f;

    for (int k0 = 0; k0 < K; k0 += BK) {
#pragma unroll
        for (int i = 0; i < (BM*BK)/THREADS; i++) {
            int idx = tid + i*THREADS;
            int m = idx / BK, k = idx % BK;
            float v = A[(bm + m)*K + k0 + k];
            if (A2) v += A2[(bm + m)*K + k0 + k];
            As[k][m] = v;
        }
#pragma unroll
        for (int i = 0; i < (BN*BK)/THREADS; i++) {
            int idx = tid + i*THREADS;
            int n = idx / BK, k = idx % BK;
            Bs[k][n] = W[(bn + n)*K + k0 + k];
        }
        __syncthreads();
#pragma unroll
        for (int k = 0; k < BK; k++) {
            float rm[TM], rn[TN];
#pragma unroll
            for (int i = 0; i < TM/4; i++) {
                float4 v = *reinterpret_cast<const float4*>(&As[k][tmi*TM + 4*i]);
                rm[4*i] = v.x; rm[4*i+1] = v.y; rm[4*i+2] = v.z; rm[4*i+3] = v.w;
            }
#pragma unroll
            for (int i = 0; i < TN/4; i++) {
                float4 v = *reinterpret_cast<const float4*>(&Bs[k][tni*TN + 4*i]);
                rn[4*i] = v.x; rn[4*i+1] = v.y; rn[4*i+2] = v.z; rn[4*i+3] = v.w;
            }
#pragma unroll
            for (int i = 0; i < TM; i++)
#pragma unroll
                for (int j = 0; j < TN; j++)
                    acc[i][j] = fmaf(rm[i], rn[j], acc[i][j]);
        }
        __syncthreads();
    }

#pragma unroll
    for (int i = 0; i < TM; i++) {
        int row = bm + tmi*TM + i;
#pragma unroll
        for (int j = 0; j < TN; j++) {
            int col = bn + tni*TN + j;
            float c = acc[i][j];
            if (bias) c += bias[col];
            if (relu) c = fmaxf(c, 0.f);
            C[row*N + col] = c;
        }
    }
}

// ---------------- causal depthwise conv(4) + silu; writes [B,L,DI] and [B,DI,L] ---
__global__ void conv_silu_kernel(const float* __restrict__ cw, const float* __restrict__ cb)
{
    __shared__ float sx[35][32];
    __shared__ float so[32][33];
    const int b = blockIdx.z, l0 = blockIdx.y*32, d0 = blockIdx.x*32;
    const int tx = threadIdx.x, ty = threadIdx.y;
    const int tid = ty*32 + tx;

    for (int i = tid; i < 35*32; i += 256) {
        int r = i >> 5, dd = i & 31;
        int l = l0 - 3 + r;
        sx[r][dd] = (l >= 0) ? g_xz[(b*LSEQ + l)*2*DI + d0 + dd] : 0.f;
    }
    const float w0 = cw[(d0+tx)*4+0], w1 = cw[(d0+tx)*4+1];
    const float w2 = cw[(d0+tx)*4+2], w3 = cw[(d0+tx)*4+3];
    const float bias = cb[d0+tx];
    __syncthreads();
#pragma unroll
    for (int j = 0; j < 4; j++) {
        int ll = ty + j*8;
        float a = bias + sx[ll][tx]*w0 + sx[ll+1][tx]*w1 + sx[ll+2][tx]*w2 + sx[ll+3][tx]*w3;
        float v = siluf(a);
        g_xc[(b*LSEQ + l0 + ll)*DI + d0 + tx] = v;
        so[ll][tx] = v;
    }
    __syncthreads();
#pragma unroll
    for (int j = 0; j < 4; j++) {
        int dd = ty + j*8;
        g_xcT[(b*DI + d0 + dd)*LSEQ + l0 + tx] = so[tx][dd];
    }
}

// ---------------- repack B,C from g_dbl into interleaved float2 buffer ------------
__global__ void repack_bc_kernel()
{
    int i = blockIdx.x*blockDim.x + threadIdx.x;   // M_TOT*16 threads
    int m = i >> 4, s = i & 15;
    reinterpret_cast<float2*>(g_bc)[i] =
        make_float2(g_dbl[m*64 + 32 + s], g_dbl[m*64 + 48 + s]);
}

// ---------------- dt = softplus(dbl[:, :32] @ dpw^T + dpb), transposed store ------
__global__ void dtproj_kernel(const float* __restrict__ dpw, const float* __restrict__ dpb)
{
    __shared__ float sdbl[32][33];
    __shared__ float sw  [32][33];
    __shared__ float so  [32][33];
    const int b = blockIdx.z, l0 = blockIdx.y*32, d0 = blockIdx.x*32;
    const int tx = threadIdx.x, ty = threadIdx.y;
    const int tid = ty*32 + tx;

    for (int i = tid; i < 1024; i += 256) {
        int r = i >> 5, c = i & 31;
        sdbl[r][c] = g_dbl[(b*LSEQ + l0 + r)*64 + c];
        sw[r][c]   = dpw[(d0 + r)*32 + c];
    }
    __syncthreads();
    const float bias = dpb[d0 + tx];
#pragma unroll
    for (int j = 0; j < 4; j++) {
        int ll = ty + j*8;
        float a = bias;
#pragma unroll
        for (int r = 0; r < 32; r++) a = fmaf(sdbl[ll][r], sw[tx][r], a);
        float sp = (a > 20.f) ? a : log1pf(__expf(a));
        so[ll][tx] = sp;
    }
    __syncthreads();
#pragma unroll
    for (int j = 0; j < 4; j++) {
        int dd = ty + j*8;
        g_dtT[(b*DI + d0 + dd)*LSEQ + l0 + tx] = so[tx][dd];
    }
}

// ---------------- selective scan: thread per (b, d, s); 16-lane reduce ------------
__global__ void scan_kernel(const float* __restrict__ Alog, const float* __restrict__ Dp)
{
    const int t = blockIdx.x*blockDim.x + threadIdx.x;  // BB*DI*16 threads
    const int s  = t & 15;
    const int ch = t >> 4;
    const int d  = ch & (DI - 1);
    const int b  = ch >> 10;

    const float a  = -__expf(Alog[d*DSTATE + s]);
    const float Dv = Dp[d];
    const float4* dt4 = reinterpret_cast<const float4*>(g_dtT + (b*DI + d)*LSEQ);
    const float4* xc4 = reinterpret_cast<const float4*>(g_xcT + (b*DI + d)*LSEQ);
    const float2* bcp = reinterpret_cast<const float2*>(g_bc) + (b*LSEQ)*16 + s;
    float4* yo = reinterpret_cast<float4*>(g_yT + (b*DI + d)*LSEQ);

    float h = 0.f;
    for (int l4 = 0; l4 < LSEQ/4; ++l4) {
        float4 dtv = dt4[l4];
        float4 xcv = xc4[l4];
        const float* dts = &dtv.x;
        const float* xcs = &xcv.x;
        float yv[4];
#pragma unroll
        for (int j = 0; j < 4; j++) {
            float dtj = dts[j], xcj = xcs[j];
            float2 bcv = bcp[(l4*4 + j)*16];
            float e = __expf(a * dtj);
            h = fmaf(e, h, dtj * bcv.x * xcj);
            float v = h * bcv.y;
            v += __shfl_xor_sync(0xffffffffu, v, 8, 16);
            v += __shfl_xor_sync(0xffffffffu, v, 4, 16);
            v += __shfl_xor_sync(0xffffffffu, v, 2, 16);
            v += __shfl_xor_sync(0xffffffffu, v, 1, 16);
            yv[j] = v + Dv * xcj;
        }
        if (s == 0) yo[l4] = make_float4(yv[0], yv[1], yv[2], yv[3]);
    }
}

// ---------------- gating: yg[b,l,d] = yT[b,d,l] * silu(z[b,l,d]) ------------------
__global__ void gate_kernel()
{
    __shared__ float sy[32][33];
    const int b = blockIdx.z, l0 = blockIdx.y*32, d0 = blockIdx.x*32;
    const int tx = threadIdx.x, ty = threadIdx.y;
#pragma unroll
    for (int j = 0; j < 4; j++) {
        int dd = ty + j*8;
        sy[tx][dd] = g_yT[(b*DI + d0 + dd)*LSEQ + l0 + tx];
    }
    __syncthreads();
#pragma unroll
    for (int j = 0; j < 4; j++) {
        int ll = ty + j*8;
        float z = g_xz[(b*LSEQ + l0 + ll)*2*DI + DI + d0 + tx];
        g_yg[(b*LSEQ + l0 + ll)*DI + d0 + tx] = sy[ll][tx] * siluf(z);
    }
}

// ---------------- host driver -----------------------------------------------------
extern "C" void kernel_launch(void* const* d_in, const int* in_sizes, int n_in,
                              void* d_out, int out_size)
{
    const float* x    = (const float*)d_in[0];
    const float* ipw  = (const float*)d_in[1];
    const float* cw   = (const float*)d_in[2];
    const float* cb   = (const float*)d_in[3];
    const float* xpw  = (const float*)d_in[4];
    const float* dpw  = (const float*)d_in[5];
    const float* dpb  = (const float*)d_in[6];
    const float* Alog = (const float*)d_in[7];
    const float* Dp   = (const float*)d_in[8];
    const float* opw  = (const float*)d_in[9];
    const float* w1   = (const float*)d_in[10];
    const float* b1   = (const float*)d_in[11];
    const float* w2   = (const float*)d_in[12];
    const float* b2   = (const float*)d_in[13];
    float* out = (float*)d_out;

    float *p_xz, *p_xc, *p_dbl, *p_yg, *p_x1, *p_x2, *p_ff;
    cudaGetSymbolAddress((void**)&p_xz,  g_xz);
    cudaGetSymbolAddress((void**)&p_xc,  g_xc);
    cudaGetSymbolAddress((void**)&p_dbl, g_dbl);
    cudaGetSymbolAddress((void**)&p_yg,  g_yg);
    cudaGetSymbolAddress((void**)&p_x1,  g_x1);
    cudaGetSymbolAddress((void**)&p_x2,  g_x2);
    cudaGetSymbolAddress((void**)&p_ff,  g_ff);

    const float* lin = x;
    float* louts[2] = {p_x1, p_x2};
    for (int i = 0; i < NL; i++) {
        // 1) in_proj: xz = x @ ipw^T   [4096,512] x [2048,512]^T
        sgemm_kernel<128,128,8,8,8><<<dim3(2*DI/128, M_TOT/128), 256>>>(
            lin, nullptr, ipw + i*2*DI*DM, nullptr, p_xz, M_TOT, 2*DI, DM, 0);
        // 2) causal depthwise conv + silu (-> g_xc, g_xcT)
        conv_silu_kernel<<<dim3(DI/32, LSEQ/32, BB), dim3(32,8)>>>(cw + i*DI*4, cb + i*DI);
        // 3) x_proj: dbl = xc @ xpw^T  [4096,1024] x [64,1024]^T
        sgemm_kernel<64,64,8,4,4><<<dim3(1, M_TOT/64), 256>>>(
            p_xc, nullptr, xpw + i*64*DI, nullptr, p_dbl, M_TOT, 64, DI, 0);
        // 4) repack B,C interleaved
        repack_bc_kernel<<<(M_TOT*16)/256, 256>>>();
        // 5) dt = softplus(dbl[:, :32] @ dpw^T + dpb) -> g_dtT
        dtproj_kernel<<<dim3(DI/32, LSEQ/32, BB), dim3(32,8)>>>(dpw + i*DI*DTR, dpb + i*DI);
        // 6) selective scan -> g_yT (includes D*xin term)
        scan_kernel<<<(BB*DI*16)/256, 256>>>(Alog + i*DI*DSTATE, Dp + i*DI);
        // 7) gating with silu(z) -> g_yg
        gate_kernel<<<dim3(DI/32, LSEQ/32, BB), dim3(32,8)>>>();
        // 8) out_proj: x_next = yg @ opw^T  [4096,1024] x [512,1024]^T
        sgemm_kernel<128,128,8,8,8><<<dim3(DM/128, M_TOT/128), 256>>>(
            p_yg, nullptr, opw + i*DM*DI, nullptr, louts[i], M_TOT, DM, DI, 0);
        lin = louts[i];
    }
    // MLP with fused residual (h = x2 + x_orig): relu(h@w1^T + b1) @ w2^T + b2
    sgemm_kernel<128,128,8,8,8><<<dim3(FF/128, M_TOT/128), 256>>>(
        p_x2, x, w1, b1, p_ff, M_TOT, FF, DM, 1);
    sgemm_kernel<128,128,8,8,8><<<dim3(DM/128, M_TOT/128), 256>>>(
        p_ff, nullptr, w2, b2, out, M_TOT, DM, FF, 0);
}

// round 4
// speedup vs baseline: 2.1162x; 2.1162x over previous
#include <cuda_runtime.h>
#include <cstdint>

#define BB 2
#define LSEQ 2048
#define DM 512
#define DI 1024
#define DSTATE 16
#define DTR 32
#define FF 1024
#define NL 2
#define M_TOT (BB*LSEQ)   // 4096

// ---------------- scratch (static device globals; no allocation) ----------------
__device__ float g_xz [BB*LSEQ*2*DI];   // in_proj output: [B,L,2*DI] (xin | z)
__device__ float g_xc [BB*LSEQ*DI];     // conv+silu, [B,L,DI]
__device__ float g_xcT[BB*LSEQ*DI];     // conv+silu, transposed [B,DI,L]
__device__ float g_dbl[BB*LSEQ*64];     // x_proj output [B*L, 64] (dt|B|C)
__device__ float g_bc [BB*LSEQ*32];     // interleaved (B,C) pairs [B*L][16] float2
__device__ float g_dtT[BB*LSEQ*DI];     // softplus(dt) transposed [B,DI,L]
__device__ float g_yT [BB*LSEQ*DI];     // scan output transposed [B,DI,L]
__device__ float g_yg [BB*LSEQ*DI];     // gated y [B,L,DI]
__device__ float g_x1 [BB*LSEQ*DM];
__device__ float g_x2 [BB*LSEQ*DM];
__device__ float g_ff [BB*LSEQ*FF];

__device__ __forceinline__ float siluf(float x) { return x / (1.f + __expf(-x)); }

__device__ __forceinline__ uint32_t f2tf32(float x) {
    uint32_t r;
    asm("cvt.rna.tf32.f32 %0, %1;" : "=r"(r) : "f"(x));
    return r;
}

__device__ __forceinline__ void mma_tf32(float* d, const uint32_t* a, const uint32_t* b) {
    asm volatile(
        "mma.sync.aligned.m16n8k8.row.col.f32.tf32.tf32.f32 "
        "{%0,%1,%2,%3}, {%4,%5,%6,%7}, {%8,%9}, {%0,%1,%2,%3};"
        : "+f"(d[0]), "+f"(d[1]), "+f"(d[2]), "+f"(d[3])
        : "r"(a[0]), "r"(a[1]), "r"(a[2]), "r"(a[3]), "r"(b[0]), "r"(b[1]));
}

// ---------------- TF32 tensor-core GEMM: C = (A (+A2)) * W^T (+bias)(relu) -------
// A: [M,K] row-major, W: [N,K] row-major, C: [M,N].
// Block tile 128x128x32, 256 threads = 8 warps (2x4), warp tile 64x32.
// Requires: M%128==0, N%128==0, K%32==0.
__global__ __launch_bounds__(256, 2)
void tf32_gemm_kernel(const float* __restrict__ A, const float* __restrict__ A2,
                      const float* __restrict__ W, const float* __restrict__ bias,
                      float* __restrict__ C, int M, int N, int K, int relu)
{
    __shared__ __align__(16) uint32_t As[128*36];   // [m][k], pad 36
    __shared__ __align__(16) uint32_t Bs[128*36];   // [n][k], pad 36

    const int tid  = threadIdx.x;
    const int warp = tid >> 5, lane = tid & 31;
    const int g = lane >> 2, t = lane & 3;
    const int wm = (warp >> 2) * 64;   // 0 or 64
    const int wn = (warp & 3) * 32;    // 0..96
    const int bm = blockIdx.y * 128;
    const int bn = blockIdx.x * 128;

    float d[4][4][4];
#pragma unroll
    for (int mi = 0; mi < 4; mi++)
#pragma unroll
        for (int ni = 0; ni < 4; ni++)
#pragma unroll
            for (int r = 0; r < 4; r++) d[mi][ni][r] = 0.f;

    for (int k0 = 0; k0 < K; k0 += 32) {
        // A tile: 128 rows x 32 k, float4 per thread x4, coalesced
#pragma unroll
        for (int i = 0; i < 4; i++) {
            int linear = tid + i*256;          // 0..1023 float4 slots
            int m  = linear >> 3;
            int kc = (linear & 7) * 4;
            float4 v = *reinterpret_cast<const float4*>(&A[(bm + m)*K + k0 + kc]);
            if (A2) {
                float4 w = *reinterpret_cast<const float4*>(&A2[(bm + m)*K + k0 + kc]);
                v.x += w.x; v.y += w.y; v.z += w.z; v.w += w.w;
            }
            uint4 u;
            u.x = f2tf32(v.x); u.y = f2tf32(v.y); u.z = f2tf32(v.z); u.w = f2tf32(v.w);
            *reinterpret_cast<uint4*>(&As[m*36 + kc]) = u;
        }
        // B tile: 128 n-rows x 32 k — W is [N][K] row-major: direct copy, no transpose
#pragma unroll
        for (int i = 0; i < 4; i++) {
            int linear = tid + i*256;
            int n  = linear >> 3;
            int kc = (linear & 7) * 4;
            float4 v = *reinterpret_cast<const float4*>(&W[(bn + n)*K + k0 + kc]);
            uint4 u;
            u.x = f2tf32(v.x); u.y = f2tf32(v.y); u.z = f2tf32(v.z); u.w = f2tf32(v.w);
            *reinterpret_cast<uint4*>(&Bs[n*36 + kc]) = u;
        }
        __syncthreads();

#pragma unroll
        for (int ks = 0; ks < 4; ks++) {
            const int kk = ks * 8;
            uint32_t a[4][4], b[4][2];
#pragma unroll
            for (int mi = 0; mi < 4; mi++) {
                const uint32_t* p0 = &As[(wm + mi*16 + g    )*36 + kk + t];
                const uint32_t* p1 = &As[(wm + mi*16 + g + 8)*36 + kk + t];
                a[mi][0] = p0[0]; a[mi][1] = p1[0];
                a[mi][2] = p0[4]; a[mi][3] = p1[4];
            }
#pragma unroll
            for (int ni = 0; ni < 4; ni++) {
                const uint32_t* p = &Bs[(wn + ni*8 + g)*36 + kk + t];
                b[ni][0] = p[0]; b[ni][1] = p[4];
            }
#pragma unroll
            for (int mi = 0; mi < 4; mi++)
#pragma unroll
                for (int ni = 0; ni < 4; ni++)
                    mma_tf32(d[mi][ni], a[mi], b[ni]);
        }
        __syncthreads();
    }

    // epilogue: c0=(g,2t) c1=(g,2t+1) c2=(g+8,2t) c3=(g+8,2t+1)
#pragma unroll
    for (int mi = 0; mi < 4; mi++) {
        int row0 = bm + wm + mi*16 + g;
        int row1 = row0 + 8;
#pragma unroll
        for (int ni = 0; ni < 4; ni++) {
            int col = bn + wn + ni*8 + 2*t;
            float c0 = d[mi][ni][0], c1 = d[mi][ni][1];
            float c2 = d[mi][ni][2], c3 = d[mi][ni][3];
            if (bias) {
                float b0 = bias[col], b1 = bias[col+1];
                c0 += b0; c1 += b1; c2 += b0; c3 += b1;
            }
            if (relu) {
                c0 = fmaxf(c0, 0.f); c1 = fmaxf(c1, 0.f);
                c2 = fmaxf(c2, 0.f); c3 = fmaxf(c3, 0.f);
            }
            *reinterpret_cast<float2*>(&C[row0*N + col]) = make_float2(c0, c1);
            *reinterpret_cast<float2*>(&C[row1*N + col]) = make_float2(c2, c3);
        }
    }
}

// ---------------- small fp32 SGEMM (x_proj): C = A * W^T --------------------------
template<int BM, int BN, int BK, int TM, int TN>
__global__ __launch_bounds__((BM/TM)*(BN/TN))
void sgemm_kernel(const float* __restrict__ A, const float* __restrict__ W,
                  float* __restrict__ C, int M, int N, int K)
{
    constexpr int THREADS = (BM/TM)*(BN/TN);
    __shared__ __align__(16) float As[BK][BM];
    __shared__ __align__(16) float Bs[BK][BN];
    const int tid = threadIdx.x;
    const int bm = blockIdx.y * BM;
    const int bn = blockIdx.x * BN;
    const int tni = tid % (BN/TN);
    const int tmi = tid / (BN/TN);

    float acc[TM][TN];
#pragma unroll
    for (int i = 0; i < TM; i++)
#pragma unroll
        for (int j = 0; j < TN; j++) acc[i][j] = 0.f;

    for (int k0 = 0; k0 < K; k0 += BK) {
#pragma unroll
        for (int i = 0; i < (BM*BK)/THREADS; i++) {
            int idx = tid + i*THREADS;
            int m = idx / BK, k = idx % BK;
            As[k][m] = A[(bm + m)*K + k0 + k];
        }
#pragma unroll
        for (int i = 0; i < (BN*BK)/THREADS; i++) {
            int idx = tid + i*THREADS;
            int n = idx / BK, k = idx % BK;
            Bs[k][n] = W[(bn + n)*K + k0 + k];
        }
        __syncthreads();
#pragma unroll
        for (int k = 0; k < BK; k++) {
            float rm[TM], rn[TN];
#pragma unroll
            for (int i = 0; i < TM/4; i++) {
                float4 v = *reinterpret_cast<const float4*>(&As[k][tmi*TM + 4*i]);
                rm[4*i] = v.x; rm[4*i+1] = v.y; rm[4*i+2] = v.z; rm[4*i+3] = v.w;
            }
#pragma unroll
            for (int i = 0; i < TN/4; i++) {
                float4 v = *reinterpret_cast<const float4*>(&Bs[k][tni*TN + 4*i]);
                rn[4*i] = v.x; rn[4*i+1] = v.y; rn[4*i+2] = v.z; rn[4*i+3] = v.w;
            }
#pragma unroll
            for (int i = 0; i < TM; i++)
#pragma unroll
                for (int j = 0; j < TN; j++)
                    acc[i][j] = fmaf(rm[i], rn[j], acc[i][j]);
        }
        __syncthreads();
    }
#pragma unroll
    for (int i = 0; i < TM; i++) {
        int row = bm + tmi*TM + i;
#pragma unroll
        for (int j = 0; j < TN; j++)
            C[row*N + bn + tni*TN + j] = acc[i][j];
    }
}

// ---------------- causal depthwise conv(4) + silu; writes [B,L,DI] and [B,DI,L] ---
__global__ void conv_silu_kernel(const float* __restrict__ cw, const float* __restrict__ cb)
{
    __shared__ float sx[35][32];
    __shared__ float so[32][33];
    const int b = blockIdx.z, l0 = blockIdx.y*32, d0 = blockIdx.x*32;
    const int tx = threadIdx.x, ty = threadIdx.y;
    const int tid = ty*32 + tx;

    for (int i = tid; i < 35*32; i += 256) {
        int r = i >> 5, dd = i & 31;
        int l = l0 - 3 + r;
        sx[r][dd] = (l >= 0) ? g_xz[(b*LSEQ + l)*2*DI + d0 + dd] : 0.f;
    }
    const float w0 = cw[(d0+tx)*4+0], w1 = cw[(d0+tx)*4+1];
    const float w2 = cw[(d0+tx)*4+2], w3 = cw[(d0+tx)*4+3];
    const float bias = cb[d0+tx];
    __syncthreads();
#pragma unroll
    for (int j = 0; j < 4; j++) {
        int ll = ty + j*8;
        float a = bias + sx[ll][tx]*w0 + sx[ll+1][tx]*w1 + sx[ll+2][tx]*w2 + sx[ll+3][tx]*w3;
        float v = siluf(a);
        g_xc[(b*LSEQ + l0 + ll)*DI + d0 + tx] = v;
        so[ll][tx] = v;
    }
    __syncthreads();
#pragma unroll
    for (int j = 0; j < 4; j++) {
        int dd = ty + j*8;
        g_xcT[(b*DI + d0 + dd)*LSEQ + l0 + tx] = so[tx][dd];
    }
}

// ---------------- repack B,C from g_dbl into interleaved float2 buffer ------------
__global__ void repack_bc_kernel()
{
    int i = blockIdx.x*blockDim.x + threadIdx.x;   // M_TOT*16 threads
    int m = i >> 4, s = i & 15;
    reinterpret_cast<float2*>(g_bc)[i] =
        make_float2(g_dbl[m*64 + 32 + s], g_dbl[m*64 + 48 + s]);
}

// ---------------- dt = softplus(dbl[:, :32] @ dpw^T + dpb), transposed store ------
__global__ void dtproj_kernel(const float* __restrict__ dpw, const float* __restrict__ dpb)
{
    __shared__ float sdbl[32][33];
    __shared__ float sw  [32][33];
    __shared__ float so  [32][33];
    const int b = blockIdx.z, l0 = blockIdx.y*32, d0 = blockIdx.x*32;
    const int tx = threadIdx.x, ty = threadIdx.y;
    const int tid = ty*32 + tx;

    for (int i = tid; i < 1024; i += 256) {
        int r = i >> 5, c = i & 31;
        sdbl[r][c] = g_dbl[(b*LSEQ + l0 + r)*64 + c];
        sw[r][c]   = dpw[(d0 + r)*32 + c];
    }
    __syncthreads();
    const float bias = dpb[d0 + tx];
#pragma unroll
    for (int j = 0; j < 4; j++) {
        int ll = ty + j*8;
        float a = bias;
#pragma unroll
        for (int r = 0; r < 32; r++) a = fmaf(sdbl[ll][r], sw[tx][r], a);
        float sp = (a > 20.f) ? a : log1pf(__expf(a));
        so[ll][tx] = sp;
    }
    __syncthreads();
#pragma unroll
    for (int j = 0; j < 4; j++) {
        int dd = ty + j*8;
        g_dtT[(b*DI + d0 + dd)*LSEQ + l0 + tx] = so[tx][dd];
    }
}

// ---------------- selective scan: thread per (b, d, s); 16-lane reduce ------------
__global__ void scan_kernel(const float* __restrict__ Alog, const float* __restrict__ Dp)
{
    const int t = blockIdx.x*blockDim.x + threadIdx.x;  // BB*DI*16 threads
    const int s  = t & 15;
    const int ch = t >> 4;
    const int d  = ch & (DI - 1);
    const int b  = ch >> 10;

    const float a  = -__expf(Alog[d*DSTATE + s]);
    const float Dv = Dp[d];
    const float4* dt4 = reinterpret_cast<const float4*>(g_dtT + (b*DI + d)*LSEQ);
    const float4* xc4 = reinterpret_cast<const float4*>(g_xcT + (b*DI + d)*LSEQ);
    const float2* bcp = reinterpret_cast<const float2*>(g_bc) + (b*LSEQ)*16 + s;
    float4* yo = reinterpret_cast<float4*>(g_yT + (b*DI + d)*LSEQ);

    float h = 0.f;
    for (int l4 = 0; l4 < LSEQ/4; ++l4) {
        float4 dtv = dt4[l4];
        float4 xcv = xc4[l4];
        const float* dts = &dtv.x;
        const float* xcs = &xcv.x;
        float yv[4];
#pragma unroll
        for (int j = 0; j < 4; j++) {
            float dtj = dts[j], xcj = xcs[j];
            float2 bcv = bcp[(l4*4 + j)*16];
            float e = __expf(a * dtj);
            h = fmaf(e, h, dtj * bcv.x * xcj);
            float v = h * bcv.y;
            v += __shfl_xor_sync(0xffffffffu, v, 8, 16);
            v += __shfl_xor_sync(0xffffffffu, v, 4, 16);
            v += __shfl_xor_sync(0xffffffffu, v, 2, 16);
            v += __shfl_xor_sync(0xffffffffu, v, 1, 16);
            yv[j] = v + Dv * xcj;
        }
        if (s == 0) yo[l4] = make_float4(yv[0], yv[1], yv[2], yv[3]);
    }
}

// ---------------- gating: yg[b,l,d] = yT[b,d,l] * silu(z[b,l,d]) ------------------
__global__ void gate_kernel()
{
    __shared__ float sy[32][33];
    const int b = blockIdx.z, l0 = blockIdx.y*32, d0 = blockIdx.x*32;
    const int tx = threadIdx.x, ty = threadIdx.y;
#pragma unroll
    for (int j = 0; j < 4; j++) {
        int dd = ty + j*8;
        sy[tx][dd] = g_yT[(b*DI + d0 + dd)*LSEQ + l0 + tx];
    }
    __syncthreads();
#pragma unroll
    for (int j = 0; j < 4; j++) {
        int ll = ty + j*8;
        float z = g_xz[(b*LSEQ + l0 + ll)*2*DI + DI + d0 + tx];
        g_yg[(b*LSEQ + l0 + ll)*DI + d0 + tx] = sy[ll][tx] * siluf(z);
    }
}

// ---------------- host driver -----------------------------------------------------
extern "C" void kernel_launch(void* const* d_in, const int* in_sizes, int n_in,
                              void* d_out, int out_size)
{
    const float* x    = (const float*)d_in[0];
    const float* ipw  = (const float*)d_in[1];
    const float* cw   = (const float*)d_in[2];
    const float* cb   = (const float*)d_in[3];
    const float* xpw  = (const float*)d_in[4];
    const float* dpw  = (const float*)d_in[5];
    const float* dpb  = (const float*)d_in[6];
    const float* Alog = (const float*)d_in[7];
    const float* Dp   = (const float*)d_in[8];
    const float* opw  = (const float*)d_in[9];
    const float* w1   = (const float*)d_in[10];
    const float* b1   = (const float*)d_in[11];
    const float* w2   = (const float*)d_in[12];
    const float* b2   = (const float*)d_in[13];
    float* out = (float*)d_out;

    float *p_xz, *p_xc, *p_dbl, *p_yg, *p_x1, *p_x2, *p_ff;
    cudaGetSymbolAddress((void**)&p_xz,  g_xz);
    cudaGetSymbolAddress((void**)&p_xc,  g_xc);
    cudaGetSymbolAddress((void**)&p_dbl, g_dbl);
    cudaGetSymbolAddress((void**)&p_yg,  g_yg);
    cudaGetSymbolAddress((void**)&p_x1,  g_x1);
    cudaGetSymbolAddress((void**)&p_x2,  g_x2);
    cudaGetSymbolAddress((void**)&p_ff,  g_ff);

    const float* lin = x;
    float* louts[2] = {p_x1, p_x2};
    for (int i = 0; i < NL; i++) {
        // 1) in_proj: xz = x @ ipw^T   [4096,512] x [2048,512]^T  (tensor cores)
        tf32_gemm_kernel<<<dim3(2*DI/128, M_TOT/128), 256>>>(
            lin, nullptr, ipw + i*2*DI*DM, nullptr, p_xz, M_TOT, 2*DI, DM, 0);
        // 2) causal depthwise conv + silu (-> g_xc, g_xcT)
        conv_silu_kernel<<<dim3(DI/32, LSEQ/32, BB), dim3(32,8)>>>(cw + i*DI*4, cb + i*DI);
        // 3) x_proj: dbl = xc @ xpw^T  [4096,1024] x [64,1024]^T  (small, SIMT)
        sgemm_kernel<64,64,8,4,4><<<dim3(1, M_TOT/64), 256>>>(
            p_xc, xpw + i*64*DI, p_dbl, M_TOT, 64, DI);
        // 4) repack B,C interleaved
        repack_bc_kernel<<<(M_TOT*16)/256, 256>>>();
        // 5) dt = softplus(dbl[:, :32] @ dpw^T + dpb) -> g_dtT
        dtproj_kernel<<<dim3(DI/32, LSEQ/32, BB), dim3(32,8)>>>(dpw + i*DI*DTR, dpb + i*DI);
        // 6) selective scan -> g_yT (includes D*xin term)
        scan_kernel<<<(BB*DI*16)/256, 256>>>(Alog + i*DI*DSTATE, Dp + i*DI);
        // 7) gating with silu(z) -> g_yg
        gate_kernel<<<dim3(DI/32, LSEQ/32, BB), dim3(32,8)>>>();
        // 8) out_proj: x_next = yg @ opw^T  [4096,1024] x [512,1024]^T  (tensor cores)
        tf32_gemm_kernel<<<dim3(DM/128, M_TOT/128), 256>>>(
            p_yg, nullptr, opw + i*DM*DI, nullptr, louts[i], M_TOT, DM, DI, 0);
        lin = louts[i];
    }
    // MLP with fused residual (h = x2 + x_orig): relu(h@w1^T + b1) @ w2^T + b2
    tf32_gemm_kernel<<<dim3(FF/128, M_TOT/128), 256>>>(
        p_x2, x, w1, b1, p_ff, M_TOT, FF, DM, 1);
    tf32_gemm_kernel<<<dim3(DM/128, M_TOT/128), 256>>>(
        p_ff, nullptr, w2, b2, out, M_TOT, DM, FF, 0);
}